// round 8
// baseline (speedup 1.0000x reference)
#include <cuda_runtime.h>

#define BATCH 4
#define NPTS 8192
#define G 32
#define NBINS (G * G)               // 1024
#define H 0.25f
#define HINV 4.0f
#define GLO -4.0f
#define SORT_THREADS 1024
#define NN_THREADS 256
#define NN_BLOCKS ((8 * NPTS) / NN_THREADS)   // 256
#define FULLMASK 0xffffffffu
#define BIG 3.0e38f

// Points sorted by (cx,cy) cell, quads (x,y,z,|p|^2), per (set,batch).
__device__ float4 g_pts[8][NPTS];
__device__ int g_cstart[8][NBINS + 1];
__device__ float g_bsum[NN_BLOCKS];
__device__ unsigned g_count;          // zero-init; reset each run

__device__ __forceinline__ int cellof(float v) {
    int c = (int)floorf((v - GLO) * HINV);
    return min(max(c, 0), G - 1);
}

// ---------------------------------------------------------------------------
// Counting sort by 2D cell (cx*32+cy). One block per (set,batch).
// ---------------------------------------------------------------------------
__global__ __launch_bounds__(SORT_THREADS)
void sort_kernel(const float* __restrict__ p1, const float* __restrict__ p2) {
    __shared__ unsigned hist[NBINS];       // 4 KB (1 bin per thread)
    __shared__ unsigned wtot[32];
    const int tid = threadIdx.x, lane = tid & 31, wid = tid >> 5;
    const int set = blockIdx.x >> 2;
    const int b = blockIdx.x & 3;
    const float* __restrict__ P = (set ? p2 : p1) + (size_t)b * NPTS * 3;

    hist[tid] = 0;
    __syncthreads();

    float xv[8], yv[8], zv[8];
#pragma unroll
    for (int k = 0; k < 8; k++) {
        int i = tid + k * SORT_THREADS;
        xv[k] = P[3 * i]; yv[k] = P[3 * i + 1]; zv[k] = P[3 * i + 2];
        atomicAdd(&hist[cellof(xv[k]) * G + cellof(yv[k])], 1u);
    }
    __syncthreads();

    // Exclusive scan over 1024 bins (1/thread).
    unsigned s = hist[tid];
    unsigned v = s;
#pragma unroll
    for (int o = 1; o < 32; o <<= 1) {
        unsigned n = __shfl_up_sync(FULLMASK, v, o);
        if (lane >= o) v += n;
    }
    if (lane == 31) wtot[wid] = v;
    __syncthreads();
    if (tid < 32) {
        unsigned w = wtot[tid];
#pragma unroll
        for (int o = 1; o < 32; o <<= 1) {
            unsigned n = __shfl_up_sync(FULLMASK, w, o);
            if (tid >= o) w += n;
        }
        wtot[tid] = w;
    }
    __syncthreads();
    unsigned excl = v - s + (wid ? wtot[wid - 1] : 0u);
    __syncthreads();
    hist[tid] = excl;

    // Publish cell starts, then BARRIER before scatter mutates hist.
    int* cs = g_cstart[blockIdx.x];
    cs[tid] = (int)excl;
    if (tid == 0) cs[NBINS] = NPTS;
    __syncthreads();                       // <-- fix: no scatter until cs published

    float4* dst = g_pts[blockIdx.x];
#pragma unroll
    for (int k = 0; k < 8; k++) {
        unsigned pos = atomicAdd(&hist[cellof(xv[k]) * G + cellof(yv[k])], 1u);
        dst[pos] = make_float4(xv[k], yv[k], zv[k],
            xv[k] * xv[k] + yv[k] * yv[k] + zv[k] * zv[k]);
    }
}

// ---------------------------------------------------------------------------
// NN: per-thread expanding Chebyshev ring search over the 2D cell grid.
// ---------------------------------------------------------------------------
__global__ __launch_bounds__(NN_THREADS)
void nn_kernel(float* __restrict__ out) {
    __shared__ float sred[8];
    __shared__ bool s_last;

    const int tid = threadIdx.x, lane = tid & 31, wid = tid >> 5;
    const int db  = blockIdx.y;            // dir*4 + b
    const int dir = db >> 2, b = db & 3;
    const float4* __restrict__ Q = g_pts[(dir ? 4 : 0) + b];
    const float4* __restrict__ T = g_pts[(dir ? 0 : 4) + b];
    const int* __restrict__ cs   = g_cstart[(dir ? 0 : 4) + b];

    const int qi = blockIdx.x * NN_THREADS + tid;
    const float4 q = Q[qi];                // queries in cell-sorted order
    const float qx = q.x, qy = q.y, qsq = q.w;
    const float m2x = -2.f * q.x, m2y = -2.f * q.y, m2z = -2.f * q.z;
    const int cx = cellof(qx), cy = cellof(qy);

    float bestv = BIG;                     // min of (|t|^2 - 2 q.t)

    // Scan contiguous cell range [y0..y1] in column xc (4-way ILP).
    auto scan_seg = [&](int xc, int y0, int y1) {
        int i = cs[xc * G + y0];
        const int e = cs[xc * G + y1 + 1];
        float b0 = bestv, b1 = BIG, b2 = BIG, b3 = BIG;
        for (; i + 3 < e; i += 4) {
            float4 t0 = T[i], t1 = T[i + 1], t2 = T[i + 2], t3 = T[i + 3];
            b0 = fminf(b0, fmaf(m2x, t0.x, fmaf(m2y, t0.y, fmaf(m2z, t0.z, t0.w))));
            b1 = fminf(b1, fmaf(m2x, t1.x, fmaf(m2y, t1.y, fmaf(m2z, t1.z, t1.w))));
            b2 = fminf(b2, fmaf(m2x, t2.x, fmaf(m2y, t2.y, fmaf(m2z, t2.z, t2.w))));
            b3 = fminf(b3, fmaf(m2x, t3.x, fmaf(m2y, t3.y, fmaf(m2z, t3.z, t3.w))));
        }
        for (; i < e; i++) {
            float4 t = T[i];
            b0 = fminf(b0, fmaf(m2x, t.x, fmaf(m2y, t.y, fmaf(m2z, t.z, t.w))));
        }
        bestv = fminf(fminf(b0, b1), fminf(b2, b3));
    };

    scan_seg(cx, cy, cy);                  // own cell (ring 0)

    for (int k = 1; k <= G; k++) {
        // Certificate for scanned box radius r = k-1 (exact box-edge margins).
        const int r = k - 1;
        float mlx = (cx - r <= 0)     ? BIG : qx - (GLO + (cx - r) * H);
        float mhx = (cx + r >= G - 1) ? BIG : (GLO + (cx + r + 1) * H) - qx;
        float mly = (cy - r <= 0)     ? BIG : qy - (GLO + (cy - r) * H);
        float mhy = (cy + r >= G - 1) ? BIG : (GLO + (cy + r + 1) * H) - qy;
        float m = fminf(fminf(mlx, mhx), fminf(mly, mhy)) - 1e-4f;
        if (m > 0.f && m * m >= bestv + qsq) break;
        if (k == G) break;                 // box radius G-1 covers the grid

        // Ring k (clipped sides skipped; columns include corners).
        const int y0 = max(cy - k, 0), y1 = min(cy + k, G - 1);
        if (cx - k >= 0)     scan_seg(cx - k, y0, y1);
        if (cx + k <= G - 1) scan_seg(cx + k, y0, y1);
        const int x0 = max(cx - k + 1, 0), x1 = min(cx + k - 1, G - 1);
        if (cy - k >= 0)
            for (int xc = x0; xc <= x1; xc++) scan_seg(xc, cy - k, cy - k);
        if (cy + k <= G - 1)
            for (int xc = x0; xc <= x1; xc++) scan_seg(xc, cy + k, cy + k);
    }

    float d2 = bestv + qsq;                // exact min squared distance

    // Reduction: per-block partials, last block folds all.
#pragma unroll
    for (int o = 16; o; o >>= 1) d2 += __shfl_down_sync(FULLMASK, d2, o);
    if (lane == 0) sred[wid] = d2;
    __syncthreads();
    if (tid == 0) {
        float w = 0.f;
#pragma unroll
        for (int i = 0; i < NN_THREADS / 32; i++) w += sred[i];
        g_bsum[blockIdx.y * gridDim.x + blockIdx.x] = w;
        __threadfence();
        unsigned t = atomicAdd(&g_count, 1u);
        s_last = (t == NN_BLOCKS - 1);
    }
    __syncthreads();

    if (s_last) {
        __threadfence();
        float w = g_bsum[tid];             // NN_BLOCKS == NN_THREADS == 256
#pragma unroll
        for (int o = 16; o; o >>= 1) w += __shfl_down_sync(FULLMASK, w, o);
        if (lane == 0) sred[wid] = w;
        __syncthreads();
        if (tid == 0) {
            float tot = 0.f;
#pragma unroll
            for (int i = 0; i < NN_THREADS / 32; i++) tot += sred[i];
            out[0] = tot;
            g_count = 0u;                  // reset for next graph replay
        }
    }
}

extern "C" void kernel_launch(void* const* d_in, const int* in_sizes, int n_in,
                              void* d_out, int out_size) {
    const float* p1 = (const float*)d_in[0];
    const float* p2 = (const float*)d_in[1];
    float* out = (float*)d_out;

    sort_kernel<<<8, SORT_THREADS>>>(p1, p2);
    nn_kernel<<<dim3(NPTS / NN_THREADS, 8), NN_THREADS>>>(out);
}